// round 2
// baseline (speedup 1.0000x reference)
#include <cuda_runtime.h>

// ---------------------------------------------------------------------------
// Problem constants
// ---------------------------------------------------------------------------
#define BB    4
#define NSEQ  2048
#define MSEQ  512
#define HH    12
#define DD    64
#define DIMV  768
#define TRIPLE 2304
#define BH    (BB*HH)          // 48
#define SCALEF 0.125f
#define TEMPF  24.0f
#define NEGF  (-1e9f)

// Output segment offsets (floats)
#define OUT1_OFF 0
#define OUT2_OFF (BB*NSEQ*DIMV)                 // 6291456
#define OUT3_OFF (OUT2_OFF + BB*MSEQ*DIMV)      // 7864320
#define OUT4_OFF (OUT3_OFF + BB*DIMV)           // 7867392

// ---------------------------------------------------------------------------
// Device scratch (no cudaMalloc allowed)
// ---------------------------------------------------------------------------
__device__ float g_tq[BB*HH*NSEQ*DD];
__device__ float g_tk[BB*HH*NSEQ*DD];
__device__ float g_tv[BB*HH*NSEQ*DD];
__device__ float g_kq[BB*HH*MSEQ*DD];
__device__ float g_kk[BB*HH*MSEQ*DD];
__device__ float g_kv[BB*HH*MSEQ*DD];
__device__ float g_cq[BB*HH*DD];
__device__ float g_ck[BB*HH*DD];
__device__ float g_cv[BB*HH*DD];
__device__ float g_dots1[BB*HH*NSEQ*MSEQ];   // later overwritten with attn
__device__ float g_dots2[BB*HH*MSEQ*NSEQ];   // later overwritten with k_attn
__device__ float g_attO[BB*NSEQ*DIMV];
__device__ float g_kO[BB*MSEQ*DIMV];
__device__ float g_cO[BB*DIMV];
__device__ float g_mx1[BB*HH*NSEQ];
__device__ float g_s1 [BB*HH*NSEQ];
__device__ float g_sh1[BB*HH*NSEQ];
__device__ float g_mx2[BB*HH*MSEQ];
__device__ float g_s2 [BB*HH*MSEQ];

// ---------------------------------------------------------------------------
// QKV GEMM:  C[rows,2304] = A[rows,768] @ W[768,2304], scatter to q/k/v
//   q/k/v layout: [b, h, s, d]  (s = position within seq)
// ---------------------------------------------------------------------------
__global__ void __launch_bounds__(256) qkv_gemm(
    const float* __restrict__ A, const float* __restrict__ W,
    float* __restrict__ oq, float* __restrict__ ok2, float* __restrict__ ov,
    int rows, int seq)
{
    __shared__ float As[16][132];
    __shared__ float Bs[16][132];
    int tid = threadIdx.x;
    int rowBase = blockIdx.y * 128;
    int colBase = blockIdx.x * 128;
    int trow = tid >> 4, tcol = tid & 15;
    float acc[8][8];
#pragma unroll
    for (int i = 0; i < 8; i++)
#pragma unroll
        for (int j = 0; j < 8; j++) acc[i][j] = 0.f;

    int aRow = tid >> 2, aCol = (tid & 3) << 2;
    int bRow = tid >> 5, bCol = (tid & 31) << 2;

    for (int kk = 0; kk < DIMV; kk += 16) {
#pragma unroll
        for (int it = 0; it < 2; ++it) {
            int r = rowBase + aRow + it * 64;
            float4 v = make_float4(0.f, 0.f, 0.f, 0.f);
            if (r < rows) v = *(const float4*)(A + (size_t)r * DIMV + kk + aCol);
            As[aCol + 0][aRow + it * 64] = v.x;
            As[aCol + 1][aRow + it * 64] = v.y;
            As[aCol + 2][aRow + it * 64] = v.z;
            As[aCol + 3][aRow + it * 64] = v.w;
        }
#pragma unroll
        for (int it = 0; it < 2; ++it) {
            int kr = bRow + it * 8;
            float4 v = *(const float4*)(W + (size_t)(kk + kr) * TRIPLE + colBase + bCol);
            *(float4*)&Bs[kr][bCol] = v;
        }
        __syncthreads();
#pragma unroll
        for (int k = 0; k < 16; k++) {
            float ra[8], rb[8];
#pragma unroll
            for (int i = 0; i < 8; i++) ra[i] = As[k][trow * 8 + i];
#pragma unroll
            for (int j = 0; j < 8; j++) rb[j] = Bs[k][tcol * 8 + j];
#pragma unroll
            for (int i = 0; i < 8; i++)
#pragma unroll
                for (int j = 0; j < 8; j++) acc[i][j] += ra[i] * rb[j];
        }
        __syncthreads();
    }

#pragma unroll
    for (int i = 0; i < 8; i++) {
        int r = rowBase + trow * 8 + i;
        if (r >= rows) break;
        int b = r / seq, s = r % seq;
#pragma unroll
        for (int j = 0; j < 8; j++) {
            int c = colBase + tcol * 8 + j;
            int part = c / DIMV, cc = c % DIMV;
            int h = cc >> 6, d = cc & 63;
            int idx = ((b * HH + h) * seq + s) * DD + d;
            float v = acc[i][j];
            if (part == 0) oq[idx] = v;
            else if (part == 1) ok2[idx] = v;
            else ov[idx] = v;
        }
    }
}

// ---------------------------------------------------------------------------
// Projection GEMM: out[rows,768] = A[rows,768] @ W[768,768] + bias
// ---------------------------------------------------------------------------
__global__ void __launch_bounds__(256) proj_gemm(
    const float* __restrict__ A, const float* __restrict__ W,
    const float* __restrict__ bias, float* __restrict__ outp, int rows)
{
    __shared__ float As[16][132];
    __shared__ float Bs[16][132];
    int tid = threadIdx.x;
    int rowBase = blockIdx.y * 128;
    int colBase = blockIdx.x * 128;
    int trow = tid >> 4, tcol = tid & 15;
    float acc[8][8];
#pragma unroll
    for (int i = 0; i < 8; i++)
#pragma unroll
        for (int j = 0; j < 8; j++) acc[i][j] = 0.f;

    int aRow = tid >> 2, aCol = (tid & 3) << 2;
    int bRow = tid >> 5, bCol = (tid & 31) << 2;

    for (int kk = 0; kk < DIMV; kk += 16) {
#pragma unroll
        for (int it = 0; it < 2; ++it) {
            int r = rowBase + aRow + it * 64;
            float4 v = make_float4(0.f, 0.f, 0.f, 0.f);
            if (r < rows) v = *(const float4*)(A + (size_t)r * DIMV + kk + aCol);
            As[aCol + 0][aRow + it * 64] = v.x;
            As[aCol + 1][aRow + it * 64] = v.y;
            As[aCol + 2][aRow + it * 64] = v.z;
            As[aCol + 3][aRow + it * 64] = v.w;
        }
#pragma unroll
        for (int it = 0; it < 2; ++it) {
            int kr = bRow + it * 8;
            float4 v = *(const float4*)(W + (size_t)(kk + kr) * DIMV + colBase + bCol);
            *(float4*)&Bs[kr][bCol] = v;
        }
        __syncthreads();
#pragma unroll
        for (int k = 0; k < 16; k++) {
            float ra[8], rb[8];
#pragma unroll
            for (int i = 0; i < 8; i++) ra[i] = As[k][trow * 8 + i];
#pragma unroll
            for (int j = 0; j < 8; j++) rb[j] = Bs[k][tcol * 8 + j];
#pragma unroll
            for (int i = 0; i < 8; i++)
#pragma unroll
                for (int j = 0; j < 8; j++) acc[i][j] += ra[i] * rb[j];
        }
        __syncthreads();
    }

#pragma unroll
    for (int i = 0; i < 8; i++) {
        int r = rowBase + trow * 8 + i;
        if (r >= rows) break;
#pragma unroll
        for (int j = 0; j < 8; j++) {
            int c = colBase + tcol * 8 + j;
            outp[(size_t)r * DIMV + c] = acc[i][j] + bias[c];
        }
    }
}

// ---------------------------------------------------------------------------
// Batched NT GEMM for dots:  C[r,c] = scale * A[r,:64] . B[c,:64], masked.
//   mask element index within (b,h): n*MSEQ + m  ->  r*mrs + c*mcs
// ---------------------------------------------------------------------------
__global__ void __launch_bounds__(256) dots_gemm(
    const float* __restrict__ Aall, const float* __restrict__ Ball,
    const int* __restrict__ mask, float* __restrict__ outAll,
    int rowsC, int colsC, int mrs, int mcs)
{
    int bh = blockIdx.z;
    const float* A = Aall + (size_t)bh * rowsC * DD;
    const float* Bm = Ball + (size_t)bh * colsC * DD;
    const int* mk = mask + (size_t)bh * NSEQ * MSEQ;
    float* outp = outAll + (size_t)bh * rowsC * colsC;

    __shared__ float As[16][132];
    __shared__ float Bs[16][132];
    int tid = threadIdx.x;
    int rowBase = blockIdx.y * 128;
    int colBase = blockIdx.x * 128;
    int trow = tid >> 4, tcol = tid & 15;
    float acc[8][8];
#pragma unroll
    for (int i = 0; i < 8; i++)
#pragma unroll
        for (int j = 0; j < 8; j++) acc[i][j] = 0.f;

    int aRow = tid >> 2, aCol = (tid & 3) << 2;

    for (int kk = 0; kk < DD; kk += 16) {
#pragma unroll
        for (int it = 0; it < 2; ++it) {
            int r = rowBase + aRow + it * 64;
            float4 v = *(const float4*)(A + (size_t)r * DD + kk + aCol);
            As[aCol + 0][aRow + it * 64] = v.x;
            As[aCol + 1][aRow + it * 64] = v.y;
            As[aCol + 2][aRow + it * 64] = v.z;
            As[aCol + 3][aRow + it * 64] = v.w;
        }
#pragma unroll
        for (int it = 0; it < 2; ++it) {
            int c = colBase + aRow + it * 64;
            float4 v = *(const float4*)(Bm + (size_t)c * DD + kk + aCol);
            Bs[aCol + 0][aRow + it * 64] = v.x;
            Bs[aCol + 1][aRow + it * 64] = v.y;
            Bs[aCol + 2][aRow + it * 64] = v.z;
            Bs[aCol + 3][aRow + it * 64] = v.w;
        }
        __syncthreads();
#pragma unroll
        for (int k = 0; k < 16; k++) {
            float ra[8], rb[8];
#pragma unroll
            for (int i = 0; i < 8; i++) ra[i] = As[k][trow * 8 + i];
#pragma unroll
            for (int j = 0; j < 8; j++) rb[j] = Bs[k][tcol * 8 + j];
#pragma unroll
            for (int i = 0; i < 8; i++)
#pragma unroll
                for (int j = 0; j < 8; j++) acc[i][j] += ra[i] * rb[j];
        }
        __syncthreads();
    }

#pragma unroll
    for (int i = 0; i < 8; i++) {
        int r = rowBase + trow * 8 + i;
#pragma unroll
        for (int j = 0; j < 8; j++) {
            int c = colBase + tcol * 8 + j;
            float v = acc[i][j] * SCALEF;
            if (mk[r * mrs + c * mcs]) v = NEGF;
            outp[(size_t)r * colsC + c] = v;
        }
    }
}

// ---------------------------------------------------------------------------
// Batched AV GEMM: C[rowsC,64] = A[rowsC,K] @ V[K,64]; write merged [b,s,h*64+d]
// ---------------------------------------------------------------------------
__global__ void __launch_bounds__(256) av_gemm(
    const float* __restrict__ Aall, const float* __restrict__ Vall,
    float* __restrict__ outp, int rowsC, int Kdim, int seq)
{
    int bh = blockIdx.y;
    int b = bh / HH, h = bh % HH;
    const float* A = Aall + (size_t)bh * rowsC * Kdim;
    const float* V = Vall + (size_t)bh * Kdim * DD;

    __shared__ float As[16][132];
    __shared__ float Bs[16][68];
    int tid = threadIdx.x;
    int rowBase = blockIdx.x * 128;
    int trow = tid >> 4, tcol = tid & 15;
    float acc[8][4];
#pragma unroll
    for (int i = 0; i < 8; i++)
#pragma unroll
        for (int j = 0; j < 4; j++) acc[i][j] = 0.f;

    int aRow = tid >> 2, aCol = (tid & 3) << 2;
    int vRow = tid >> 4, vCol = (tid & 15) << 2;

    for (int kk = 0; kk < Kdim; kk += 16) {
#pragma unroll
        for (int it = 0; it < 2; ++it) {
            int r = rowBase + aRow + it * 64;
            float4 v = *(const float4*)(A + (size_t)r * Kdim + kk + aCol);
            As[aCol + 0][aRow + it * 64] = v.x;
            As[aCol + 1][aRow + it * 64] = v.y;
            As[aCol + 2][aRow + it * 64] = v.z;
            As[aCol + 3][aRow + it * 64] = v.w;
        }
        {
            float4 v = *(const float4*)(V + (size_t)(kk + vRow) * DD + vCol);
            *(float4*)&Bs[vRow][vCol] = v;
        }
        __syncthreads();
#pragma unroll
        for (int k = 0; k < 16; k++) {
            float ra[8], rb[4];
#pragma unroll
            for (int i = 0; i < 8; i++) ra[i] = As[k][trow * 8 + i];
#pragma unroll
            for (int j = 0; j < 4; j++) rb[j] = Bs[k][tcol * 4 + j];
#pragma unroll
            for (int i = 0; i < 8; i++)
#pragma unroll
                for (int j = 0; j < 4; j++) acc[i][j] += ra[i] * rb[j];
        }
        __syncthreads();
    }

#pragma unroll
    for (int i = 0; i < 8; i++) {
        int r = rowBase + trow * 8 + i;
#pragma unroll
        for (int j = 0; j < 4; j++) {
            int d = tcol * 4 + j;
            outp[(size_t)(b * seq + r) * DIMV + h * 64 + d] = acc[i][j];
        }
    }
}

// ---------------------------------------------------------------------------
// Softmax stats, branch 1: per row (length 512): max, sum exp, sum exp(24*)
// one warp per row
// ---------------------------------------------------------------------------
__global__ void __launch_bounds__(256) stats1_kernel()
{
    int gw = (blockIdx.x * 256 + threadIdx.x) >> 5;
    int lane = threadIdx.x & 31;
    const float* row = g_dots1 + (size_t)gw * MSEQ;
    float v[16], m = -3.4e38f;
#pragma unroll
    for (int i = 0; i < 16; i++) { v[i] = row[lane + 32 * i]; m = fmaxf(m, v[i]); }
#pragma unroll
    for (int o = 16; o > 0; o >>= 1) m = fmaxf(m, __shfl_xor_sync(0xffffffffu, m, o));
    float s = 0.f, sh = 0.f;
#pragma unroll
    for (int i = 0; i < 16; i++) {
        float t = v[i] - m;
        s += __expf(t);
        sh += __expf(TEMPF * t);
    }
#pragma unroll
    for (int o = 16; o > 0; o >>= 1) {
        s  += __shfl_xor_sync(0xffffffffu, s, o);
        sh += __shfl_xor_sync(0xffffffffu, sh, o);
    }
    if (lane == 0) { g_mx1[gw] = m; g_s1[gw] = s; g_sh1[gw] = sh; }
}

// ---------------------------------------------------------------------------
// Softmax stats, branch 2: per row (length 2048): max, sum exp
// ---------------------------------------------------------------------------
__global__ void __launch_bounds__(256) stats2_kernel()
{
    int gw = (blockIdx.x * 256 + threadIdx.x) >> 5;
    int lane = threadIdx.x & 31;
    const float* row = g_dots2 + (size_t)gw * NSEQ;
    float m = -3.4e38f;
#pragma unroll
    for (int i = 0; i < 64; i++) m = fmaxf(m, row[lane + 32 * i]);
#pragma unroll
    for (int o = 16; o > 0; o >>= 1) m = fmaxf(m, __shfl_xor_sync(0xffffffffu, m, o));
    float s = 0.f;
#pragma unroll
    for (int i = 0; i < 64; i++) s += __expf(row[lane + 32 * i] - m);
#pragma unroll
    for (int o = 16; o > 0; o >>= 1) s += __shfl_xor_sync(0xffffffffu, s, o);
    if (lane == 0) { g_mx2[gw] = m; g_s2[gw] = s; }
}

// ---------------------------------------------------------------------------
// Branch-1 apply: 32x32 tile transpose.
//   attn[n,m]   = exp(d-mx)/s1 * krd[m,n]      -> overwrite g_dots1 (n-major)
//   hot [m,n]   = exp(24(d-mx))/sh * krd[m,n]  -> out4 [b,h,m,n]
// ---------------------------------------------------------------------------
__global__ void apply1_kernel(const float* __restrict__ krd, float* __restrict__ out4)
{
    __shared__ float sd[32][33];
    __shared__ float sk[32][33];
    __shared__ float smx[32], ss1[32], ssh[32];
    int bh = blockIdx.z;
    int n0 = blockIdx.x * 32, m0 = blockIdx.y * 32;
    int tx = threadIdx.x, ty = threadIdx.y;
    const float* dbase = g_dots1 + (size_t)bh * NSEQ * MSEQ;
    const float* kbase = krd + (size_t)bh * MSEQ * NSEQ;

    int t = ty * 32 + tx;
    if (t < 32) {
        smx[t] = g_mx1[bh * NSEQ + n0 + t];
        ss1[t] = g_s1 [bh * NSEQ + n0 + t];
        ssh[t] = g_sh1[bh * NSEQ + n0 + t];
    }
#pragma unroll
    for (int it = 0; it < 4; it++) {
        int l = ty + 8 * it;
        sd[l][tx] = dbase[(size_t)(n0 + l) * MSEQ + m0 + tx];
        sk[l][tx] = kbase[(size_t)(m0 + l) * NSEQ + n0 + tx];
    }
    __syncthreads();

    // attn (n-major, coalesced along m)
#pragma unroll
    for (int it = 0; it < 4; it++) {
        int nl = ty + 8 * it;
        float e = __expf(sd[nl][tx] - smx[nl]);
        float a = e / ss1[nl] * sk[tx][nl];
        g_dots1[(size_t)bh * NSEQ * MSEQ + (size_t)(n0 + nl) * MSEQ + m0 + tx] = a;
    }
    // hot (m-major, coalesced along n) -> output 4
#pragma unroll
    for (int it = 0; it < 4; it++) {
        int ml = ty + 8 * it;
        float e = __expf(TEMPF * (sd[tx][ml] - smx[tx]));
        float hv = e / ssh[tx] * sk[ml][tx];
        out4[(size_t)bh * MSEQ * NSEQ + (size_t)(m0 + ml) * NSEQ + n0 + tx] = hv;
    }
}

// ---------------------------------------------------------------------------
// Branch-2 apply (elementwise, dots2 & krd share [b,h,m,n] layout)
// ---------------------------------------------------------------------------
__global__ void __launch_bounds__(256) apply2_kernel(const float* __restrict__ krd)
{
    int i = blockIdx.x * 256 + threadIdx.x;     // float4 index
    int row = i >> 9;                            // (i*4)/2048
    float m = g_mx2[row];
    float inv = 1.f / g_s2[row];
    float4 dv = ((const float4*)g_dots2)[i];
    float4 kr = ((const float4*)krd)[i];
    dv.x = __expf(dv.x - m) * inv * kr.x;
    dv.y = __expf(dv.y - m) * inv * kr.y;
    dv.z = __expf(dv.z - m) * inv * kr.z;
    dv.w = __expf(dv.w - m) * inv * kr.w;
    ((float4*)g_dots2)[i] = dv;
}

// ---------------------------------------------------------------------------
// Branch 3: cluster query vs kernel keys. One block per (b,h).
// ---------------------------------------------------------------------------
__global__ void __launch_bounds__(256) cluster_kernel(const int* __restrict__ mask)
{
    int bh = blockIdx.x;
    int b = bh / HH, h = bh % HH;
    __shared__ float q[64];
    __shared__ float p[512];
    __shared__ float red[256];
    int tid = threadIdx.x;
    const float* cq = g_cq + bh * 64;
    const float* kk = g_kk + (size_t)bh * MSEQ * DD;
    const float* kv = g_kv + (size_t)bh * MSEQ * DD;

    if (tid < 64) q[tid] = cq[tid];
    __syncthreads();

    for (int m = tid; m < MSEQ; m += 256) {
        float acc = 0.f;
#pragma unroll
        for (int d = 0; d < 64; d++) acc += q[d] * kk[m * 64 + d];
        acc *= SCALEF;
        if (mask[(size_t)bh * NSEQ * MSEQ + m]) acc = NEGF;
        p[m] = acc;
    }
    __syncthreads();

    red[tid] = fmaxf(p[tid], p[tid + 256]);
    __syncthreads();
    for (int s = 128; s > 0; s >>= 1) {
        if (tid < s) red[tid] = fmaxf(red[tid], red[tid + s]);
        __syncthreads();
    }
    float mx = red[0];
    __syncthreads();

    float e0 = __expf(p[tid] - mx), e1 = __expf(p[tid + 256] - mx);
    p[tid] = e0; p[tid + 256] = e1;
    red[tid] = e0 + e1;
    __syncthreads();
    for (int s = 128; s > 0; s >>= 1) {
        if (tid < s) red[tid] += red[tid + s];
        __syncthreads();
    }
    float inv = 1.f / red[0];
    __syncthreads();

    int d = tid & 63, part = tid >> 6;
    float acc = 0.f;
    for (int m = part * 128; m < part * 128 + 128; m++) acc += p[m] * kv[m * 64 + d];
    red[tid] = acc * inv;
    __syncthreads();
    if (part == 0)
        g_cO[b * DIMV + h * 64 + d] = red[d] + red[64 + d] + red[128 + d] + red[192 + d];
}

// ---------------------------------------------------------------------------
// Host launcher
// ---------------------------------------------------------------------------
extern "C" void kernel_launch(void* const* d_in, const int* in_sizes, int n_in,
                              void* d_out, int out_size)
{
    const float* x    = (const float*)d_in[0];
    const float* kx   = (const float*)d_in[1];
    const float* krd  = (const float*)d_in[2];
    const float* clst = (const float*)d_in[3];
    const int*   mask = (const int*)d_in[4];
    const float* Wqkv = (const float*)d_in[5];
    const float* Wout = (const float*)d_in[6];
    const float* bout = (const float*)d_in[7];
    float* out  = (float*)d_out;
    float* out1 = out + OUT1_OFF;
    float* out2 = out + OUT2_OFF;
    float* out3 = out + OUT3_OFF;
    float* out4 = out + OUT4_OFF;

    float *p_tq, *p_tk, *p_tv, *p_kq, *p_kk, *p_kv, *p_cq, *p_ck, *p_cv;
    float *p_d1, *p_d2, *p_attO, *p_kO, *p_cO;
    cudaGetSymbolAddress((void**)&p_tq, g_tq);
    cudaGetSymbolAddress((void**)&p_tk, g_tk);
    cudaGetSymbolAddress((void**)&p_tv, g_tv);
    cudaGetSymbolAddress((void**)&p_kq, g_kq);
    cudaGetSymbolAddress((void**)&p_kk, g_kk);
    cudaGetSymbolAddress((void**)&p_kv, g_kv);
    cudaGetSymbolAddress((void**)&p_cq, g_cq);
    cudaGetSymbolAddress((void**)&p_ck, g_ck);
    cudaGetSymbolAddress((void**)&p_cv, g_cv);
    cudaGetSymbolAddress((void**)&p_d1, g_dots1);
    cudaGetSymbolAddress((void**)&p_d2, g_dots2);
    cudaGetSymbolAddress((void**)&p_attO, g_attO);
    cudaGetSymbolAddress((void**)&p_kO, g_kO);
    cudaGetSymbolAddress((void**)&p_cO, g_cO);

    // 1) QKV projections
    qkv_gemm<<<dim3(TRIPLE / 128, (BB * NSEQ) / 128), 256>>>(x, Wqkv, p_tq, p_tk, p_tv, BB * NSEQ, NSEQ);
    qkv_gemm<<<dim3(TRIPLE / 128, (BB * MSEQ) / 128), 256>>>(kx, Wqkv, p_kq, p_kk, p_kv, BB * MSEQ, MSEQ);
    qkv_gemm<<<dim3(TRIPLE / 128, 1), 256>>>(clst, Wqkv, p_cq, p_ck, p_cv, BB, 1);

    // 2) dots (masked + scaled)
    dots_gemm<<<dim3(MSEQ / 128, NSEQ / 128, BH), 256>>>(p_tq, p_kk, mask, p_d1,
                                                         NSEQ, MSEQ, MSEQ, 1);
    dots_gemm<<<dim3(NSEQ / 128, MSEQ / 128, BH), 256>>>(p_kq, p_tk, mask, p_d2,
                                                         MSEQ, NSEQ, 1, MSEQ);

    // 3) softmax stats
    stats1_kernel<<<(BH * NSEQ) / 8, 256>>>();
    stats2_kernel<<<(BH * MSEQ) / 8, 256>>>();

    // 4) apply (attn / attn_hot / k_attn)
    apply1_kernel<<<dim3(NSEQ / 32, MSEQ / 32, BH), dim3(32, 8)>>>(krd, out4);
    apply2_kernel<<<(BH * MSEQ * NSEQ / 4) / 256, 256>>>(krd);

    // 5) attention-value GEMMs
    av_gemm<<<dim3(NSEQ / 128, BH), 256>>>(p_d1, p_kv, p_attO, NSEQ, MSEQ, NSEQ);
    av_gemm<<<dim3(MSEQ / 128, BH), 256>>>(p_d2, p_tv, p_kO, MSEQ, NSEQ, MSEQ);

    // 6) cluster branch
    cluster_kernel<<<BH, 256>>>(mask);

    // 7) output projections
    proj_gemm<<<dim3(DIMV / 128, (BB * NSEQ) / 128), 256>>>(p_attO, Wout, bout, out1, BB * NSEQ);
    proj_gemm<<<dim3(DIMV / 128, (BB * MSEQ) / 128), 256>>>(p_kO, Wout, bout, out2, BB * MSEQ);
    proj_gemm<<<dim3(DIMV / 128, 1), 256>>>(p_cO, Wout, bout, out3, BB);
}

// round 5
// speedup vs baseline: 1.0466x; 1.0466x over previous
#include <cuda_runtime.h>

// ---------------------------------------------------------------------------
// Problem constants
// ---------------------------------------------------------------------------
#define BB    4
#define NSEQ  2048
#define MSEQ  512
#define HH    12
#define DD    64
#define DIMV  768
#define TRIPLE 2304
#define BH    (BB*HH)          // 48
#define SCALEF 0.125f
#define TEMPF  24.0f
#define NEGF  (-1e9f)

// Output segment offsets (floats)
#define OUT1_OFF 0
#define OUT2_OFF (BB*NSEQ*DIMV)                 // 6291456
#define OUT3_OFF (OUT2_OFF + BB*MSEQ*DIMV)      // 7864320
#define OUT4_OFF (OUT3_OFF + BB*DIMV)           // 7867392

// ---------------------------------------------------------------------------
// Packed f32x2 helpers (FFMA2 — only reachable via PTX)
// ---------------------------------------------------------------------------
#define FMA_X2(d, a, b, c) \
    asm("fma.rn.f32x2 %0, %1, %2, %3;" : "=l"(d) : "l"(a), "l"(b), "l"(c))
#define PACK_DUP(p, f) \
    asm("mov.b64 %0, {%1, %2};" : "=l"(p) : "f"(f), "f"(f))
#define UNPACK_X2(lo, hi, p) \
    asm("mov.b64 {%0, %1}, %2;" : "=f"(lo), "=f"(hi) : "l"(p))

typedef unsigned long long u64t;

// ---------------------------------------------------------------------------
// Device scratch (no cudaMalloc allowed)
// ---------------------------------------------------------------------------
__device__ float g_tq[BB*HH*NSEQ*DD];
__device__ float g_tk[BB*HH*NSEQ*DD];
__device__ float g_tv[BB*HH*NSEQ*DD];
__device__ float g_kq[BB*HH*MSEQ*DD];
__device__ float g_kk[BB*HH*MSEQ*DD];
__device__ float g_kv[BB*HH*MSEQ*DD];
__device__ float g_cq[BB*HH*DD];
__device__ float g_ck[BB*HH*DD];
__device__ float g_cv[BB*HH*DD];
__device__ float g_dots1[BB*HH*NSEQ*MSEQ];   // later overwritten with attn
__device__ float g_dots2[BB*HH*MSEQ*NSEQ];   // later overwritten with k_attn
__device__ float g_attO[BB*NSEQ*DIMV];
__device__ float g_kO[BB*MSEQ*DIMV];
__device__ float g_cO[BB*DIMV];
__device__ float g_mx1[BB*HH*NSEQ];
__device__ float g_s1 [BB*HH*NSEQ];
__device__ float g_sh1[BB*HH*NSEQ];

// ---------------------------------------------------------------------------
// QKV GEMM:  C[rows,2304] = A[rows,768] @ W[768,2304], scatter to q/k/v
// f32x2 inner loop + global->reg prefetch pipeline
// ---------------------------------------------------------------------------
__global__ void __launch_bounds__(256) qkv_gemm(
    const float* __restrict__ A, const float* __restrict__ W,
    float* __restrict__ oq, float* __restrict__ ok2, float* __restrict__ ov,
    int rows, int seq)
{
    __shared__ float As[16][132];
    __shared__ float Bs[16][132];
    int tid = threadIdx.x;
    int rowBase = blockIdx.y * 128;
    int colBase = blockIdx.x * 128;
    int trow = tid >> 4, tcol = tid & 15;
    u64t acc[8][4];
#pragma unroll
    for (int i = 0; i < 8; i++)
#pragma unroll
        for (int j = 0; j < 4; j++) acc[i][j] = 0ull;

    int aRow = tid >> 2, aCol = (tid & 3) << 2;
    int bRow = tid >> 5, bCol = (tid & 31) << 2;

    float4 aReg[2], bReg[2];
    // prefetch kk = 0
#pragma unroll
    for (int it = 0; it < 2; ++it) {
        int r = rowBase + aRow + it * 64;
        aReg[it] = make_float4(0.f, 0.f, 0.f, 0.f);
        if (r < rows) aReg[it] = *(const float4*)(A + (size_t)r * DIMV + aCol);
        bReg[it] = *(const float4*)(W + (size_t)(bRow + it * 8) * TRIPLE + colBase + bCol);
    }

    for (int kk = 0; kk < DIMV; kk += 16) {
        // store staged regs to smem
#pragma unroll
        for (int it = 0; it < 2; ++it) {
            As[aCol + 0][aRow + it * 64] = aReg[it].x;
            As[aCol + 1][aRow + it * 64] = aReg[it].y;
            As[aCol + 2][aRow + it * 64] = aReg[it].z;
            As[aCol + 3][aRow + it * 64] = aReg[it].w;
            *(float4*)&Bs[bRow + it * 8][bCol] = bReg[it];
        }
        __syncthreads();
        // prefetch next tile
        if (kk + 16 < DIMV) {
#pragma unroll
            for (int it = 0; it < 2; ++it) {
                int r = rowBase + aRow + it * 64;
                aReg[it] = make_float4(0.f, 0.f, 0.f, 0.f);
                if (r < rows) aReg[it] = *(const float4*)(A + (size_t)r * DIMV + kk + 16 + aCol);
                bReg[it] = *(const float4*)(W + (size_t)(kk + 16 + bRow + it * 8) * TRIPLE + colBase + bCol);
            }
        }
#pragma unroll
        for (int k = 0; k < 16; k++) {
            u64t rbp[4];
#pragma unroll
            for (int j = 0; j < 4; j++)
                rbp[j] = *(const u64t*)&Bs[k][tcol * 8 + 2 * j];
#pragma unroll
            for (int i = 0; i < 8; i++) {
                float a = As[k][trow * 8 + i];
                u64t ap; PACK_DUP(ap, a);
#pragma unroll
                for (int j = 0; j < 4; j++) FMA_X2(acc[i][j], ap, rbp[j], acc[i][j]);
            }
        }
        __syncthreads();
    }

#pragma unroll
    for (int i = 0; i < 8; i++) {
        int r = rowBase + trow * 8 + i;
        if (r >= rows) break;
        int b = r / seq, s = r % seq;
#pragma unroll
        for (int j = 0; j < 4; j++) {
            float v0, v1;
            UNPACK_X2(v0, v1, acc[i][j]);
#pragma unroll
            for (int u = 0; u < 2; u++) {
                int c = colBase + tcol * 8 + 2 * j + u;
                float v = u ? v1 : v0;
                int part = c / DIMV, cc = c % DIMV;
                int h = cc >> 6, d = cc & 63;
                int idx = ((b * HH + h) * seq + s) * DD + d;
                if (part == 0) oq[idx] = v;
                else if (part == 1) ok2[idx] = v;
                else ov[idx] = v;
            }
        }
    }
}

// ---------------------------------------------------------------------------
// Projection GEMM: out[rows,768] = A[rows,768] @ W[768,768] + bias
// ---------------------------------------------------------------------------
__global__ void __launch_bounds__(256) proj_gemm(
    const float* __restrict__ A, const float* __restrict__ W,
    const float* __restrict__ bias, float* __restrict__ outp, int rows)
{
    __shared__ float As[16][132];
    __shared__ float Bs[16][132];
    int tid = threadIdx.x;
    int rowBase = blockIdx.y * 128;
    int colBase = blockIdx.x * 128;
    int trow = tid >> 4, tcol = tid & 15;
    u64t acc[8][4];
#pragma unroll
    for (int i = 0; i < 8; i++)
#pragma unroll
        for (int j = 0; j < 4; j++) acc[i][j] = 0ull;

    int aRow = tid >> 2, aCol = (tid & 3) << 2;
    int bRow = tid >> 5, bCol = (tid & 31) << 2;

    float4 aReg[2], bReg[2];
#pragma unroll
    for (int it = 0; it < 2; ++it) {
        int r = rowBase + aRow + it * 64;
        aReg[it] = make_float4(0.f, 0.f, 0.f, 0.f);
        if (r < rows) aReg[it] = *(const float4*)(A + (size_t)r * DIMV + aCol);
        bReg[it] = *(const float4*)(W + (size_t)(bRow + it * 8) * DIMV + colBase + bCol);
    }

    for (int kk = 0; kk < DIMV; kk += 16) {
#pragma unroll
        for (int it = 0; it < 2; ++it) {
            As[aCol + 0][aRow + it * 64] = aReg[it].x;
            As[aCol + 1][aRow + it * 64] = aReg[it].y;
            As[aCol + 2][aRow + it * 64] = aReg[it].z;
            As[aCol + 3][aRow + it * 64] = aReg[it].w;
            *(float4*)&Bs[bRow + it * 8][bCol] = bReg[it];
        }
        __syncthreads();
        if (kk + 16 < DIMV) {
#pragma unroll
            for (int it = 0; it < 2; ++it) {
                int r = rowBase + aRow + it * 64;
                aReg[it] = make_float4(0.f, 0.f, 0.f, 0.f);
                if (r < rows) aReg[it] = *(const float4*)(A + (size_t)r * DIMV + kk + 16 + aCol);
                bReg[it] = *(const float4*)(W + (size_t)(kk + 16 + bRow + it * 8) * DIMV + colBase + bCol);
            }
        }
#pragma unroll
        for (int k = 0; k < 16; k++) {
            u64t rbp[4];
#pragma unroll
            for (int j = 0; j < 4; j++)
                rbp[j] = *(const u64t*)&Bs[k][tcol * 8 + 2 * j];
#pragma unroll
            for (int i = 0; i < 8; i++) {
                float a = As[k][trow * 8 + i];
                u64t ap; PACK_DUP(ap, a);
#pragma unroll
                for (int j = 0; j < 4; j++) FMA_X2(acc[i][j], ap, rbp[j], acc[i][j]);
            }
        }
        __syncthreads();
    }

#pragma unroll
    for (int i = 0; i < 8; i++) {
        int r = rowBase + trow * 8 + i;
        if (r >= rows) break;
#pragma unroll
        for (int j = 0; j < 4; j++) {
            int c = colBase + tcol * 8 + 2 * j;
            float v0, v1;
            UNPACK_X2(v0, v1, acc[i][j]);
            float2 o = make_float2(v0 + bias[c], v1 + bias[c + 1]);
            *(float2*)(outp + (size_t)r * DIMV + c) = o;
        }
    }
}

// ---------------------------------------------------------------------------
// Batched NT GEMM for dots:  C[r,c] = scale * A[r,:64] . B[c,:64], masked.
// ---------------------------------------------------------------------------
__global__ void __launch_bounds__(256) dots_gemm(
    const float* __restrict__ Aall, const float* __restrict__ Ball,
    const int* __restrict__ mask, float* __restrict__ outAll,
    int rowsC, int colsC, int mrs, int mcs)
{
    int bh = blockIdx.z;
    const float* A = Aall + (size_t)bh * rowsC * DD;
    const float* Bm = Ball + (size_t)bh * colsC * DD;
    const int* mk = mask + (size_t)bh * NSEQ * MSEQ;
    float* outp = outAll + (size_t)bh * rowsC * colsC;

    __shared__ float As[16][132];
    __shared__ float Bs[16][132];
    int tid = threadIdx.x;
    int rowBase = blockIdx.y * 128;
    int colBase = blockIdx.x * 128;
    int trow = tid >> 4, tcol = tid & 15;
    u64t acc[8][4];
#pragma unroll
    for (int i = 0; i < 8; i++)
#pragma unroll
        for (int j = 0; j < 4; j++) acc[i][j] = 0ull;

    int aRow = tid >> 2, aCol = (tid & 3) << 2;

    float4 aReg[2], bReg[2];
#pragma unroll
    for (int it = 0; it < 2; ++it) {
        aReg[it] = *(const float4*)(A + (size_t)(rowBase + aRow + it * 64) * DD + aCol);
        bReg[it] = *(const float4*)(Bm + (size_t)(colBase + aRow + it * 64) * DD + aCol);
    }

    for (int kk = 0; kk < DD; kk += 16) {
#pragma unroll
        for (int it = 0; it < 2; ++it) {
            As[aCol + 0][aRow + it * 64] = aReg[it].x;
            As[aCol + 1][aRow + it * 64] = aReg[it].y;
            As[aCol + 2][aRow + it * 64] = aReg[it].z;
            As[aCol + 3][aRow + it * 64] = aReg[it].w;
            Bs[aCol + 0][aRow + it * 64] = bReg[it].x;
            Bs[aCol + 1][aRow + it * 64] = bReg[it].y;
            Bs[aCol + 2][aRow + it * 64] = bReg[it].z;
            Bs[aCol + 3][aRow + it * 64] = bReg[it].w;
        }
        __syncthreads();
        if (kk + 16 < DD) {
#pragma unroll
            for (int it = 0; it < 2; ++it) {
                aReg[it] = *(const float4*)(A + (size_t)(rowBase + aRow + it * 64) * DD + kk + 16 + aCol);
                bReg[it] = *(const float4*)(Bm + (size_t)(colBase + aRow + it * 64) * DD + kk + 16 + aCol);
            }
        }
#pragma unroll
        for (int k = 0; k < 16; k++) {
            u64t rbp[4];
#pragma unroll
            for (int j = 0; j < 4; j++)
                rbp[j] = *(const u64t*)&Bs[k][tcol * 8 + 2 * j];
#pragma unroll
            for (int i = 0; i < 8; i++) {
                float a = As[k][trow * 8 + i];
                u64t ap; PACK_DUP(ap, a);
#pragma unroll
                for (int j = 0; j < 4; j++) FMA_X2(acc[i][j], ap, rbp[j], acc[i][j]);
            }
        }
        __syncthreads();
    }

#pragma unroll
    for (int i = 0; i < 8; i++) {
        int r = rowBase + trow * 8 + i;
#pragma unroll
        for (int j = 0; j < 4; j++) {
            int c = colBase + tcol * 8 + 2 * j;
            float v0, v1;
            UNPACK_X2(v0, v1, acc[i][j]);
            v0 *= SCALEF; v1 *= SCALEF;
            if (mk[r * mrs + c * mcs]) v0 = NEGF;
            if (mk[r * mrs + (c + 1) * mcs]) v1 = NEGF;
            *(float2*)(outp + (size_t)r * colsC + c) = make_float2(v0, v1);
        }
    }
}

// ---------------------------------------------------------------------------
// Batched AV GEMM: C[rowsC,64] = A[rowsC,K] @ V[K,64]; write merged [b,s,h*64+d]
// ---------------------------------------------------------------------------
__global__ void __launch_bounds__(256) av_gemm(
    const float* __restrict__ Aall, const float* __restrict__ Vall,
    float* __restrict__ outp, int rowsC, int Kdim, int seq)
{
    int bh = blockIdx.y;
    int b = bh / HH, h = bh % HH;
    const float* A = Aall + (size_t)bh * rowsC * Kdim;
    const float* V = Vall + (size_t)bh * Kdim * DD;

    __shared__ float As[16][132];
    __shared__ float Bs[16][68];
    int tid = threadIdx.x;
    int rowBase = blockIdx.x * 128;
    int trow = tid >> 4, tcol = tid & 15;
    u64t acc[8][2];
#pragma unroll
    for (int i = 0; i < 8; i++)
#pragma unroll
        for (int j = 0; j < 2; j++) acc[i][j] = 0ull;

    int aRow = tid >> 2, aCol = (tid & 3) << 2;
    int vRow = tid >> 4, vCol = (tid & 15) << 2;

    float4 aReg[2], vReg;
#pragma unroll
    for (int it = 0; it < 2; ++it)
        aReg[it] = *(const float4*)(A + (size_t)(rowBase + aRow + it * 64) * Kdim + aCol);
    vReg = *(const float4*)(V + (size_t)vRow * DD + vCol);

    for (int kk = 0; kk < Kdim; kk += 16) {
#pragma unroll
        for (int it = 0; it < 2; ++it) {
            As[aCol + 0][aRow + it * 64] = aReg[it].x;
            As[aCol + 1][aRow + it * 64] = aReg[it].y;
            As[aCol + 2][aRow + it * 64] = aReg[it].z;
            As[aCol + 3][aRow + it * 64] = aReg[it].w;
        }
        *(float4*)&Bs[vRow][vCol] = vReg;
        __syncthreads();
        if (kk + 16 < Kdim) {
#pragma unroll
            for (int it = 0; it < 2; ++it)
                aReg[it] = *(const float4*)(A + (size_t)(rowBase + aRow + it * 64) * Kdim + kk + 16 + aCol);
            vReg = *(const float4*)(V + (size_t)(kk + 16 + vRow) * DD + vCol);
        }
#pragma unroll
        for (int k = 0; k < 16; k++) {
            u64t rbp[2];
#pragma unroll
            for (int j = 0; j < 2; j++)
                rbp[j] = *(const u64t*)&Bs[k][tcol * 4 + 2 * j];
#pragma unroll
            for (int i = 0; i < 8; i++) {
                float a = As[k][trow * 8 + i];
                u64t ap; PACK_DUP(ap, a);
#pragma unroll
                for (int j = 0; j < 2; j++) FMA_X2(acc[i][j], ap, rbp[j], acc[i][j]);
            }
        }
        __syncthreads();
    }

#pragma unroll
    for (int i = 0; i < 8; i++) {
        int r = rowBase + trow * 8 + i;
#pragma unroll
        for (int j = 0; j < 2; j++) {
            int d = tcol * 4 + 2 * j;
            float v0, v1;
            UNPACK_X2(v0, v1, acc[i][j]);
            *(float2*)(outp + (size_t)(b * seq + r) * DIMV + h * 64 + d) = make_float2(v0, v1);
        }
    }
}

// ---------------------------------------------------------------------------
// Softmax stats, branch 1: per row (length 512): max, sum exp, sum exp(24*)
// ---------------------------------------------------------------------------
__global__ void __launch_bounds__(256) stats1_kernel()
{
    int gw = (blockIdx.x * 256 + threadIdx.x) >> 5;
    int lane = threadIdx.x & 31;
    const float* row = g_dots1 + (size_t)gw * MSEQ;
    float v[16], m = -3.4e38f;
#pragma unroll
    for (int i = 0; i < 16; i++) { v[i] = row[lane + 32 * i]; m = fmaxf(m, v[i]); }
#pragma unroll
    for (int o = 16; o > 0; o >>= 1) m = fmaxf(m, __shfl_xor_sync(0xffffffffu, m, o));
    float s = 0.f, sh = 0.f;
#pragma unroll
    for (int i = 0; i < 16; i++) {
        float t = v[i] - m;
        s += __expf(t);
        sh += __expf(TEMPF * t);
    }
#pragma unroll
    for (int o = 16; o > 0; o >>= 1) {
        s  += __shfl_xor_sync(0xffffffffu, s, o);
        sh += __shfl_xor_sync(0xffffffffu, sh, o);
    }
    if (lane == 0) { g_mx1[gw] = m; g_s1[gw] = s; g_sh1[gw] = sh; }
}

// ---------------------------------------------------------------------------
// Branch-1 apply: 32x32 tile transpose.
//   attn[n,m]   = exp(d-mx)/s1 * krd[m,n]      -> overwrite g_dots1 (n-major)
//   hot [m,n]   = exp(24(d-mx))/sh * krd[m,n]  -> out4 [b,h,m,n]
// ---------------------------------------------------------------------------
__global__ void apply1_kernel(const float* __restrict__ krd, float* __restrict__ out4)
{
    __shared__ float sd[32][33];
    __shared__ float sk[32][33];
    __shared__ float smx[32], ss1[32], ssh[32];
    int bh = blockIdx.z;
    int n0 = blockIdx.x * 32, m0 = blockIdx.y * 32;
    int tx = threadIdx.x, ty = threadIdx.y;
    const float* dbase = g_dots1 + (size_t)bh * NSEQ * MSEQ;
    const float* kbase = krd + (size_t)bh * MSEQ * NSEQ;

    int t = ty * 32 + tx;
    if (t < 32) {
        smx[t] = g_mx1[bh * NSEQ + n0 + t];
        ss1[t] = g_s1 [bh * NSEQ + n0 + t];
        ssh[t] = g_sh1[bh * NSEQ + n0 + t];
    }
#pragma unroll
    for (int it = 0; it < 4; it++) {
        int l = ty + 8 * it;
        sd[l][tx] = dbase[(size_t)(n0 + l) * MSEQ + m0 + tx];
        sk[l][tx] = kbase[(size_t)(m0 + l) * NSEQ + n0 + tx];
    }
    __syncthreads();

#pragma unroll
    for (int it = 0; it < 4; it++) {
        int nl = ty + 8 * it;
        float e = __expf(sd[nl][tx] - smx[nl]);
        float a = e / ss1[nl] * sk[tx][nl];
        g_dots1[(size_t)bh * NSEQ * MSEQ + (size_t)(n0 + nl) * MSEQ + m0 + tx] = a;
    }
#pragma unroll
    for (int it = 0; it < 4; it++) {
        int ml = ty + 8 * it;
        float e = __expf(TEMPF * (sd[tx][ml] - smx[tx]));
        float hv = e / ssh[tx] * sk[ml][tx];
        out4[(size_t)bh * MSEQ * NSEQ + (size_t)(m0 + ml) * NSEQ + n0 + tx] = hv;
    }
}

// ---------------------------------------------------------------------------
// Branch-2 fused softmax + krd apply: one block per row (length 2048)
// Reads dots2 ONCE, writes k_attn in place.
// ---------------------------------------------------------------------------
__global__ void __launch_bounds__(256) softmax2_kernel(const float* __restrict__ krd)
{
    __shared__ float red[8];
    int row = blockIdx.x;
    int tid = threadIdx.x;
    int lane = tid & 31, warp = tid >> 5;
    float* drow = g_dots2 + (size_t)row * NSEQ;
    const float* krow = krd + (size_t)row * NSEQ;

    float4 v0 = ((const float4*)drow)[tid];
    float4 v1 = ((const float4*)drow)[tid + 256];
    float m = fmaxf(fmaxf(fmaxf(v0.x, v0.y), fmaxf(v0.z, v0.w)),
                    fmaxf(fmaxf(v1.x, v1.y), fmaxf(v1.z, v1.w)));
#pragma unroll
    for (int o = 16; o > 0; o >>= 1) m = fmaxf(m, __shfl_xor_sync(0xffffffffu, m, o));
    if (lane == 0) red[warp] = m;
    __syncthreads();
    m = red[lane & 7];
#pragma unroll
    for (int o = 4; o > 0; o >>= 1) m = fmaxf(m, __shfl_xor_sync(0xffffffffu, m, o));

    float e0x = __expf(v0.x - m), e0y = __expf(v0.y - m), e0z = __expf(v0.z - m), e0w = __expf(v0.w - m);
    float e1x = __expf(v1.x - m), e1y = __expf(v1.y - m), e1z = __expf(v1.z - m), e1w = __expf(v1.w - m);
    float s = e0x + e0y + e0z + e0w + e1x + e1y + e1z + e1w;
#pragma unroll
    for (int o = 16; o > 0; o >>= 1) s += __shfl_xor_sync(0xffffffffu, s, o);
    __syncthreads();
    if (lane == 0) red[warp] = s;
    __syncthreads();
    s = red[lane & 7];
#pragma unroll
    for (int o = 4; o > 0; o >>= 1) s += __shfl_xor_sync(0xffffffffu, s, o);
    float inv = 1.f / s;

    float4 k0 = ((const float4*)krow)[tid];
    float4 k1 = ((const float4*)krow)[tid + 256];
    float4 o0 = make_float4(e0x * inv * k0.x, e0y * inv * k0.y, e0z * inv * k0.z, e0w * inv * k0.w);
    float4 o1 = make_float4(e1x * inv * k1.x, e1y * inv * k1.y, e1z * inv * k1.z, e1w * inv * k1.w);
    ((float4*)drow)[tid] = o0;
    ((float4*)drow)[tid + 256] = o1;
}

// ---------------------------------------------------------------------------
// Branch 3: cluster query vs kernel keys. One block per (b,h).
// ---------------------------------------------------------------------------
__global__ void __launch_bounds__(256) cluster_kernel(const int* __restrict__ mask)
{
    int bh = blockIdx.x;
    int b = bh / HH, h = bh % HH;
    __shared__ float q[64];
    __shared__ float p[512];
    __shared__ float red[256];
    int tid = threadIdx.x;
    const float* cq = g_cq + bh * 64;
    const float* kk = g_kk + (size_t)bh * MSEQ * DD;
    const float* kv = g_kv + (size_t)bh * MSEQ * DD;

    if (tid < 64) q[tid] = cq[tid];
    __syncthreads();

    for (int m = tid; m < MSEQ; m += 256) {
        float acc = 0.f;
#pragma unroll
        for (int d = 0; d < 64; d++) acc += q[d] * kk[m * 64 + d];
        acc *= SCALEF;
        if (mask[(size_t)bh * NSEQ * MSEQ + m]) acc = NEGF;
        p[m] = acc;
    }
    __syncthreads();

    red[tid] = fmaxf(p[tid], p[tid + 256]);
    __syncthreads();
    for (int s = 128; s > 0; s >>= 1) {
        if (tid < s) red[tid] = fmaxf(red[tid], red[tid + s]);
        __syncthreads();
    }
    float mx = red[0];
    __syncthreads();

    float e0 = __expf(p[tid] - mx), e1 = __expf(p[tid + 256] - mx);
    p[tid] = e0; p[tid + 256] = e1;
    red[tid] = e0 + e1;
    __syncthreads();
    for (int s = 128; s > 0; s >>= 1) {
        if (tid < s) red[tid] += red[tid + s];
        __syncthreads();
    }
    float inv = 1.f / red[0];
    __syncthreads();

    int d = tid & 63, part = tid >> 6;
    float acc = 0.f;
    for (int m = part * 128; m < part * 128 + 128; m++) acc += p[m] * kv[m * 64 + d];
    red[tid] = acc * inv;
    __syncthreads();
    if (part == 0)
        g_cO[b * DIMV + h * 64 + d] = red[d] + red[64 + d] + red[128 + d] + red[192 + d];
}

// ---------------------------------------------------------------------------
// Host launcher
// ---------------------------------------------------------------------------
extern "C" void kernel_launch(void* const* d_in, const int* in_sizes, int n_in,
                              void* d_out, int out_size)
{
    const float* x    = (const float*)d_in[0];
    const float* kx   = (const float*)d_in[1];
    const float* krd  = (const float*)d_in[2];
    const float* clst = (const float*)d_in[3];
    const int*   mask = (const int*)d_in[4];
    const float* Wqkv = (const float*)d_in[5];
    const float* Wout = (const float*)d_in[6];
    const float* bout = (const float*)d_in[7];
    float* out  = (float*)d_out;
    float* out1 = out + OUT1_OFF;
    float* out2 = out + OUT2_OFF;
    float* out3 = out + OUT3_OFF;
    float* out4 = out + OUT4_OFF;

    float *p_tq, *p_tk, *p_tv, *p_kq, *p_kk, *p_kv, *p_cq, *p_ck, *p_cv;
    float *p_d1, *p_d2, *p_attO, *p_kO, *p_cO;
    cudaGetSymbolAddress((void**)&p_tq, g_tq);
    cudaGetSymbolAddress((void**)&p_tk, g_tk);
    cudaGetSymbolAddress((void**)&p_tv, g_tv);
    cudaGetSymbolAddress((void**)&p_kq, g_kq);
    cudaGetSymbolAddress((void**)&p_kk, g_kk);
    cudaGetSymbolAddress((void**)&p_kv, g_kv);
    cudaGetSymbolAddress((void**)&p_cq, g_cq);
    cudaGetSymbolAddress((void**)&p_ck, g_ck);
    cudaGetSymbolAddress((void**)&p_cv, g_cv);
    cudaGetSymbolAddress((void**)&p_d1, g_dots1);
    cudaGetSymbolAddress((void**)&p_d2, g_dots2);
    cudaGetSymbolAddress((void**)&p_attO, g_attO);
    cudaGetSymbolAddress((void**)&p_kO, g_kO);
    cudaGetSymbolAddress((void**)&p_cO, g_cO);

    // 1) QKV projections
    qkv_gemm<<<dim3(TRIPLE / 128, (BB * NSEQ) / 128), 256>>>(x, Wqkv, p_tq, p_tk, p_tv, BB * NSEQ, NSEQ);
    qkv_gemm<<<dim3(TRIPLE / 128, (BB * MSEQ) / 128), 256>>>(kx, Wqkv, p_kq, p_kk, p_kv, BB * MSEQ, MSEQ);
    qkv_gemm<<<dim3(TRIPLE / 128, 1), 256>>>(clst, Wqkv, p_cq, p_ck, p_cv, BB, 1);

    // 2) dots (masked + scaled)
    dots_gemm<<<dim3(MSEQ / 128, NSEQ / 128, BH), 256>>>(p_tq, p_kk, mask, p_d1,
                                                         NSEQ, MSEQ, MSEQ, 1);
    dots_gemm<<<dim3(NSEQ / 128, MSEQ / 128, BH), 256>>>(p_kq, p_tk, mask, p_d2,
                                                         MSEQ, NSEQ, 1, MSEQ);

    // 3) softmax stats (branch 1) + fused softmax (branch 2)
    stats1_kernel<<<(BH * NSEQ) / 8, 256>>>();
    softmax2_kernel<<<BH * MSEQ, 256>>>(krd);

    // 4) branch-1 apply (attn / attn_hot)
    apply1_kernel<<<dim3(NSEQ / 32, MSEQ / 32, BH), dim3(32, 8)>>>(krd, out4);

    // 5) attention-value GEMMs
    av_gemm<<<dim3(NSEQ / 128, BH), 256>>>(p_d1, p_kv, p_attO, NSEQ, MSEQ, NSEQ);
    av_gemm<<<dim3(MSEQ / 128, BH), 256>>>(p_d2, p_tv, p_kO, MSEQ, NSEQ, MSEQ);

    // 6) cluster branch
    cluster_kernel<<<BH, 256>>>(mask);

    // 7) output projections
    proj_gemm<<<dim3(DIMV / 128, (BB * NSEQ) / 128), 256>>>(p_attO, Wout, bout, out1, BB * NSEQ);
    proj_gemm<<<dim3(DIMV / 128, (BB * MSEQ) / 128), 256>>>(p_kO, Wout, bout, out2, BB * MSEQ);
    proj_gemm<<<dim3(DIMV / 128, 1), 256>>>(p_cO, Wout, bout, out3, BB);
}